// round 1
// baseline (speedup 1.0000x reference)
#include <cuda_runtime.h>
#include <cuda_bf16.h>

// Problem constants
#define T_STEPS 1000
#define BATCH   256
#define HID     512
#define NIN     3
#define NOUT    2
#define BH      (BATCH * HID)          // 131072
#define SPK_ELEMS ((size_t)T_STEPS * BH)  // 131,072,000

#define BETA    0.8f
#define THRESH  1.0f

// ---------------------------------------------------------------------------
// Kernel 1: per-(b,h) membrane scan. Grid: 512 blocks (b, half), 256 threads.
// Each thread owns one hidden unit h = half*256 + tid and iterates all 1000
// timesteps, writing the spike train directly to the output (streaming store).
// x[:, b, :] is staged in shared memory padded to float4 rows so the main loop
// does a single broadcast LDS.128 per step.
// ---------------------------------------------------------------------------
__global__ __launch_bounds__(256)
void snn_scan_kernel(const float* __restrict__ x,     // [T, B, 3]
                     const float* __restrict__ W1,    // [512, 3]
                     float* __restrict__ spk_out)     // [T, B, 512]
{
    __shared__ float sx[T_STEPS * 4];   // 16 KB, rows padded 3 -> 4

    const int b    = blockIdx.x >> 1;
    const int half = blockIdx.x & 1;
    const int tid  = threadIdx.x;
    const int h    = half * 256 + tid;

    // Stage x[:, b, :] into shared (3000 scalar loads spread over 256 threads)
    for (int idx = tid; idx < T_STEPS * NIN; idx += 256) {
        const int t = idx / 3;
        const int i = idx - t * 3;
        sx[t * 4 + i] = x[(size_t)t * (BATCH * NIN) + b * NIN + i];
    }
    __syncthreads();

    const float w0 = W1[h * 3 + 0];
    const float w1 = W1[h * 3 + 1];
    const float w2 = W1[h * 3 + 2];

    const float4* __restrict__ sx4 = reinterpret_cast<const float4*>(sx);
    float* __restrict__ out_base = spk_out + (size_t)b * HID + h;

    float mem = 0.0f;
    #pragma unroll 4
    for (int t = 0; t < T_STEPS; ++t) {
        const float4 xv = sx4[t];
        // einsum order: ((x0*w0) + x1*w1) + x2*w2
        const float cur = fmaf(xv.z, w2, fmaf(xv.y, w1, xv.x * w0));
        // reset from PREVIOUS mem (zero-reset), then integrate
        const float m2 = fmaf(BETA, mem, cur);
        mem = (mem > THRESH) ? 0.0f : m2;
        const float spk = (mem > THRESH) ? 1.0f : 0.0f;
        __stcs(out_base + (size_t)t * BH, spk);   // streaming: never re-read (except tail)
    }
}

// ---------------------------------------------------------------------------
// Kernel 2: readout over the last 10 steps. Grid: 256 blocks (one per b),
// 512 threads (one per h). Deterministic block reduction (shuffle + shared),
// sigmoid per timestep, mean over the 10 steps.
// ---------------------------------------------------------------------------
__global__ __launch_bounds__(512)
void snn_tail_kernel(const float* __restrict__ spk,   // [T, B, 512]
                     const float* __restrict__ W2,    // [2, 512]
                     float* __restrict__ avg_out)     // [B, 2]
{
    const int b   = blockIdx.x;
    const int h   = threadIdx.x;          // 0..511
    const int lane = h & 31;
    const int wid  = h >> 5;              // 0..15

    const float w_o0 = W2[h];
    const float w_o1 = W2[HID + h];

    float s[20];  // s[2*t + o]
    #pragma unroll
    for (int t = 0; t < 10; ++t) {
        const float v = spk[(size_t)(T_STEPS - 10 + t) * BH + (size_t)b * HID + h];
        s[2 * t + 0] = v * w_o0;
        s[2 * t + 1] = v * w_o1;
    }

    // warp-level tree reduction on each of the 20 partials
    #pragma unroll
    for (int j = 0; j < 20; ++j) {
        #pragma unroll
        for (int off = 16; off > 0; off >>= 1)
            s[j] += __shfl_xor_sync(0xFFFFFFFFu, s[j], off);
    }

    __shared__ float red[16][20];
    if (lane == 0) {
        #pragma unroll
        for (int j = 0; j < 20; ++j) red[wid][j] = s[j];
    }
    __syncthreads();

    __shared__ float tot[20];
    if (h < 20) {
        float v = 0.0f;
        #pragma unroll
        for (int w = 0; w < 16; ++w) v += red[w][h];
        tot[h] = v;
    }
    __syncthreads();

    if (h < NOUT) {
        float acc = 0.0f;
        #pragma unroll
        for (int t = 0; t < 10; ++t) {
            const float z = tot[2 * t + h];
            acc += 1.0f / (1.0f + expf(-z));
        }
        avg_out[b * NOUT + h] = acc * 0.1f;
    }
}

// ---------------------------------------------------------------------------
extern "C" void kernel_launch(void* const* d_in, const int* in_sizes, int n_in,
                              void* d_out, int out_size)
{
    const float* x  = (const float*)d_in[0];   // [1000, 256, 3]
    const float* W1 = (const float*)d_in[1];   // [512, 3]
    const float* W2 = (const float*)d_in[2];   // [2, 512]
    float* out = (float*)d_out;                // [spk_rec | avg_out]

    float* spk_out = out;                      // 131,072,000 floats
    float* avg_out = out + SPK_ELEMS;          // 512 floats

    snn_scan_kernel<<<512, 256>>>(x, W1, spk_out);
    snn_tail_kernel<<<BATCH, 512>>>(spk_out, W2, avg_out);
}

// round 2
// speedup vs baseline: 1.3577x; 1.3577x over previous
#include <cuda_runtime.h>
#include <cuda_bf16.h>

// Problem constants
#define T_STEPS 1000
#define BATCH   256
#define HID     512
#define NIN     3
#define NOUT    2
#define BH      (BATCH * HID)             // 131072
#define SPK_ELEMS ((size_t)T_STEPS * BH)  // 131,072,000

#define BETA    0.8f
#define THRESH  1.0f

// ---------------------------------------------------------------------------
// Kernel 1: per-(b,h) membrane scan, 2 hidden units per thread, STG.64 spikes.
// Grid: 512 blocks = (b, half); 128 threads; thread owns h = half*256 + tid*2
// and h+1. x[:, b, :] staged in shared padded to float4 rows -> one broadcast
// LDS.128 feeds both units each step.
// ---------------------------------------------------------------------------
__global__ __launch_bounds__(128)
void snn_scan_kernel(const float* __restrict__ x,     // [T, B, 3]
                     const float* __restrict__ W1,    // [512, 3]
                     float* __restrict__ spk_out)     // [T, B, 512]
{
    __shared__ float sx[T_STEPS * 4];   // 16 KB, rows padded 3 -> 4

    const int b    = blockIdx.x >> 1;
    const int half = blockIdx.x & 1;
    const int tid  = threadIdx.x;
    const int h0   = half * 256 + tid * 2;

    // Stage x[:, b, :] into shared (3000 scalar loads over 128 threads)
    for (int idx = tid; idx < T_STEPS * NIN; idx += 128) {
        const int t = idx / 3;
        const int i = idx - t * 3;
        sx[t * 4 + i] = x[(size_t)t * (BATCH * NIN) + b * NIN + i];
    }
    __syncthreads();

    const float wa0 = W1[h0 * 3 + 0];
    const float wa1 = W1[h0 * 3 + 1];
    const float wa2 = W1[h0 * 3 + 2];
    const float wb0 = W1[h0 * 3 + 3];
    const float wb1 = W1[h0 * 3 + 4];
    const float wb2 = W1[h0 * 3 + 5];

    const float4* __restrict__ sx4 = reinterpret_cast<const float4*>(sx);
    float2* __restrict__ out = reinterpret_cast<float2*>(spk_out + (size_t)b * HID + h0);

    float mem0 = 0.0f, mem1 = 0.0f;
    #pragma unroll 4
    for (int t = 0; t < T_STEPS; ++t) {
        const float4 xv = sx4[t];
        const float cur0 = fmaf(xv.z, wa2, fmaf(xv.y, wa1, xv.x * wa0));
        const float cur1 = fmaf(xv.z, wb2, fmaf(xv.y, wb1, xv.x * wb0));
        // zero-reset from PREVIOUS mem, then integrate
        const float m0n = fmaf(BETA, mem0, cur0);
        const float m1n = fmaf(BETA, mem1, cur1);
        mem0 = (mem0 > THRESH) ? 0.0f : m0n;
        mem1 = (mem1 > THRESH) ? 0.0f : m1n;
        float2 sp;
        sp.x = (mem0 > THRESH) ? 1.0f : 0.0f;
        sp.y = (mem1 > THRESH) ? 1.0f : 0.0f;
        __stcs(out + (size_t)t * (BH / 2), sp);   // streaming STG.64
    }
}

// ---------------------------------------------------------------------------
// Kernel 2: readout over the last 10 steps. Grid: 256 blocks (one per b),
// 128 threads. Stage spk tail + W2 in shared, then 4 warps x 5 (t,o) pairs,
// each pair a lane-strided dot over 512 elems + 5-shuffle reduce.
// Deterministic; reads hit L2 (data just written by kernel 1).
// ---------------------------------------------------------------------------
__global__ __launch_bounds__(128)
void snn_tail_kernel(const float* __restrict__ spk,   // [T, B, 512]
                     const float* __restrict__ W2,    // [2, 512]
                     float* __restrict__ avg_out)     // [B, 2]
{
    __shared__ float sspk[10][HID];   // 20 KB
    __shared__ float sW2[2][HID];     // 4 KB
    __shared__ float totsh[20];

    const int b    = blockIdx.x;
    const int tid  = threadIdx.x;
    const int lane = tid & 31;
    const int wid  = tid >> 5;

    // Stage the 10-step spike tail for this b: 10 x 512 floats, float4 loads
    #pragma unroll
    for (int t = 0; t < 10; ++t) {
        const float4* src = reinterpret_cast<const float4*>(
            spk + (size_t)(T_STEPS - 10 + t) * BH + (size_t)b * HID);
        reinterpret_cast<float4*>(sspk[t])[tid] = src[tid];   // 128 float4 = 512 floats
    }
    // Stage W2: 1024 floats = 256 float4
    {
        const float4* src = reinterpret_cast<const float4*>(W2);
        float4* dst = reinterpret_cast<float4*>(&sW2[0][0]);
        dst[tid]       = src[tid];
        dst[tid + 128] = src[tid + 128];
    }
    __syncthreads();

    // 20 (t,o) pairs over 4 warps, 5 pairs each
    #pragma unroll
    for (int p = 0; p < 5; ++p) {
        const int pair = wid * 5 + p;
        const int t = pair >> 1;
        const int o = pair & 1;
        float acc = 0.0f;
        #pragma unroll
        for (int i = lane; i < HID; i += 32)
            acc = fmaf(sspk[t][i], sW2[o][i], acc);
        #pragma unroll
        for (int off = 16; off > 0; off >>= 1)
            acc += __shfl_xor_sync(0xFFFFFFFFu, acc, off);
        if (lane == 0) totsh[pair] = acc;
    }
    __syncthreads();

    if (tid < NOUT) {
        float s = 0.0f;
        #pragma unroll
        for (int t = 0; t < 10; ++t) {
            const float z = totsh[2 * t + tid];
            s += 1.0f / (1.0f + expf(-z));
        }
        avg_out[b * NOUT + tid] = s * 0.1f;
    }
}

// ---------------------------------------------------------------------------
extern "C" void kernel_launch(void* const* d_in, const int* in_sizes, int n_in,
                              void* d_out, int out_size)
{
    const float* x  = (const float*)d_in[0];   // [1000, 256, 3]
    const float* W1 = (const float*)d_in[1];   // [512, 3]
    const float* W2 = (const float*)d_in[2];   // [2, 512]
    float* out = (float*)d_out;

    float* spk_out = out;                      // 131,072,000 floats
    float* avg_out = out + SPK_ELEMS;          // 512 floats

    snn_scan_kernel<<<512, 128>>>(x, W1, spk_out);
    snn_tail_kernel<<<BATCH, 128>>>(spk_out, W2, avg_out);
}

// round 3
// speedup vs baseline: 1.5443x; 1.1374x over previous
#include <cuda_runtime.h>
#include <cuda_bf16.h>

// Problem constants
#define T_STEPS 1000
#define T_MAIN  990            // steps before the readout tail
#define BATCH   256
#define HID     512
#define NIN     3
#define NOUT    2
#define BH      (BATCH * HID)             // 131072
#define SPK_ELEMS ((size_t)T_STEPS * BH)  // 131,072,000

#define BETA    0.8f
#define THRESH  1.0f

// ---------------------------------------------------------------------------
// Single fused kernel.
// Grid: 256 blocks (one per batch element b). 128 threads; each thread owns
// 4 consecutive hidden units h = tid*4 .. tid*4+3 -> STG.128 spike stores.
// x[:, b, :] staged in shared padded to float4 rows (one broadcast LDS.128
// per step feeds all 4 units). For the last 10 steps each thread also
// accumulates spk . W2 partials in registers; a block reduction then computes
// avg_out[b] = mean_t sigmoid(spk_t . W2^T) directly. No second kernel.
// ---------------------------------------------------------------------------
__global__ __launch_bounds__(128)
void snn_fused_kernel(const float* __restrict__ x,     // [T, B, 3]
                      const float* __restrict__ W1,    // [512, 3]
                      const float* __restrict__ W2,    // [2, 512]
                      float* __restrict__ spk_out,     // [T, B, 512]
                      float* __restrict__ avg_out)     // [B, 2]
{
    __shared__ float sx[T_STEPS * 4];   // 16 KB, x rows padded 3 -> 4
    __shared__ float red[4][20];        // per-warp tail partials
    __shared__ float tot[20];

    const int b    = blockIdx.x;
    const int tid  = threadIdx.x;
    const int lane = tid & 31;
    const int wid  = tid >> 5;
    const int h0   = tid * 4;

    // Stage x[:, b, :] into shared (3000 scalar loads over 128 threads)
    for (int idx = tid; idx < T_STEPS * NIN; idx += 128) {
        const int t = idx / 3;
        const int i = idx - t * 3;
        sx[t * 4 + i] = x[(size_t)t * (BATCH * NIN) + b * NIN + i];
    }
    __syncthreads();

    // W1 rows for the 4 owned hidden units: 12 contiguous floats, 16B aligned
    const float4 w1a = reinterpret_cast<const float4*>(W1 + h0 * 3)[0];
    const float4 w1b = reinterpret_cast<const float4*>(W1 + h0 * 3)[1];
    const float4 w1c = reinterpret_cast<const float4*>(W1 + h0 * 3)[2];
    // unit j weights:
    const float wA0 = w1a.x, wA1 = w1a.y, wA2 = w1a.z;
    const float wB0 = w1a.w, wB1 = w1b.x, wB2 = w1b.y;
    const float wC0 = w1b.z, wC1 = w1b.w, wC2 = w1c.x;
    const float wD0 = w1c.y, wD1 = w1c.z, wD2 = w1c.w;

    // W2 weights for the owned units (both output rows)
    const float4 w2o0 = reinterpret_cast<const float4*>(W2 + h0)[0];        // W2[0][h0..h0+3]
    const float4 w2o1 = reinterpret_cast<const float4*>(W2 + HID + h0)[0]; // W2[1][h0..h0+3]

    const float4* __restrict__ sx4 = reinterpret_cast<const float4*>(sx);
    float4* __restrict__ out = reinterpret_cast<float4*>(spk_out + (size_t)b * HID + h0);

    float m0 = 0.0f, m1 = 0.0f, m2 = 0.0f, m3 = 0.0f;

    // ---- main scan: t in [0, 990) ----
    #pragma unroll 2
    for (int t = 0; t < T_MAIN; ++t) {
        const float4 xv = sx4[t];
        const float c0 = fmaf(xv.z, wA2, fmaf(xv.y, wA1, xv.x * wA0));
        const float c1 = fmaf(xv.z, wB2, fmaf(xv.y, wB1, xv.x * wB0));
        const float c2 = fmaf(xv.z, wC2, fmaf(xv.y, wC1, xv.x * wC0));
        const float c3 = fmaf(xv.z, wD2, fmaf(xv.y, wD1, xv.x * wD0));
        // zero-reset from PREVIOUS mem, then integrate
        m0 = (m0 > THRESH) ? c0 : fmaf(BETA, m0, c0);
        m1 = (m1 > THRESH) ? c1 : fmaf(BETA, m1, c1);
        m2 = (m2 > THRESH) ? c2 : fmaf(BETA, m2, c2);
        m3 = (m3 > THRESH) ? c3 : fmaf(BETA, m3, c3);
        float4 sp;
        sp.x = (m0 > THRESH) ? 1.0f : 0.0f;
        sp.y = (m1 > THRESH) ? 1.0f : 0.0f;
        sp.z = (m2 > THRESH) ? 1.0f : 0.0f;
        sp.w = (m3 > THRESH) ? 1.0f : 0.0f;
        __stcs(out + (size_t)t * (BH / 4), sp);   // streaming STG.128
    }

    // ---- tail scan: t in [990, 1000), also accumulate readout partials ----
    float acc[20];   // acc[2*k + o] for tail step k, output o
    #pragma unroll
    for (int k = 0; k < 10; ++k) {
        const int t = T_MAIN + k;
        const float4 xv = sx4[t];
        const float c0 = fmaf(xv.z, wA2, fmaf(xv.y, wA1, xv.x * wA0));
        const float c1 = fmaf(xv.z, wB2, fmaf(xv.y, wB1, xv.x * wB0));
        const float c2 = fmaf(xv.z, wC2, fmaf(xv.y, wC1, xv.x * wC0));
        const float c3 = fmaf(xv.z, wD2, fmaf(xv.y, wD1, xv.x * wD0));
        m0 = (m0 > THRESH) ? c0 : fmaf(BETA, m0, c0);
        m1 = (m1 > THRESH) ? c1 : fmaf(BETA, m1, c1);
        m2 = (m2 > THRESH) ? c2 : fmaf(BETA, m2, c2);
        m3 = (m3 > THRESH) ? c3 : fmaf(BETA, m3, c3);
        float4 sp;
        sp.x = (m0 > THRESH) ? 1.0f : 0.0f;
        sp.y = (m1 > THRESH) ? 1.0f : 0.0f;
        sp.z = (m2 > THRESH) ? 1.0f : 0.0f;
        sp.w = (m3 > THRESH) ? 1.0f : 0.0f;
        __stcs(out + (size_t)t * (BH / 4), sp);

        // readout partials for this thread's 4 units
        float p0 = sp.x * w2o0.x; p0 = fmaf(sp.y, w2o0.y, p0);
        p0 = fmaf(sp.z, w2o0.z, p0); p0 = fmaf(sp.w, w2o0.w, p0);
        float p1 = sp.x * w2o1.x; p1 = fmaf(sp.y, w2o1.y, p1);
        p1 = fmaf(sp.z, w2o1.z, p1); p1 = fmaf(sp.w, w2o1.w, p1);
        acc[2 * k + 0] = p0;
        acc[2 * k + 1] = p1;
    }

    // ---- block reduction of the 20 partials ----
    #pragma unroll
    for (int j = 0; j < 20; ++j) {
        #pragma unroll
        for (int off = 16; off > 0; off >>= 1)
            acc[j] += __shfl_xor_sync(0xFFFFFFFFu, acc[j], off);
    }
    if (lane == 0) {
        #pragma unroll
        for (int j = 0; j < 20; ++j) red[wid][j] = acc[j];
    }
    __syncthreads();

    if (tid < 20)
        tot[tid] = red[0][tid] + red[1][tid] + red[2][tid] + red[3][tid];
    __syncthreads();

    if (tid < NOUT) {
        float s = 0.0f;
        #pragma unroll
        for (int k = 0; k < 10; ++k) {
            const float z = tot[2 * k + tid];
            s += 1.0f / (1.0f + expf(-z));
        }
        avg_out[b * NOUT + tid] = s * 0.1f;
    }
}

// ---------------------------------------------------------------------------
extern "C" void kernel_launch(void* const* d_in, const int* in_sizes, int n_in,
                              void* d_out, int out_size)
{
    const float* x  = (const float*)d_in[0];   // [1000, 256, 3]
    const float* W1 = (const float*)d_in[1];   // [512, 3]
    const float* W2 = (const float*)d_in[2];   // [2, 512]
    float* out = (float*)d_out;

    float* spk_out = out;                      // 131,072,000 floats
    float* avg_out = out + SPK_ELEMS;          // 512 floats

    snn_fused_kernel<<<BATCH, 128>>>(x, W1, W2, spk_out, avg_out);
}